// round 14
// baseline (speedup 1.0000x reference)
#include <cuda_runtime.h>
#include <cuda_bf16.h>
#include <stdint.h>

// BlankEmbedding: out[b,t,:] = emb[x[b,t]]
//   + sum_{j=1..3, t-j>=0} [x[b,t-j+1]==BLANK && x[b,t-j]!=BLANK] * emb[x[b,t-j]]
//
// B=4, S=4096, DIM=1024, VOCAB=50257, BLANK=100.
//
// prepass: one thread per row -> int4 descriptor {tok, add0, add1, add2}.
// main:    persistent blocks, grid-stride over groups of 4 rows.
//          64 threads per row, 4 float4/thread, register ping-pong
//          (steady-state MLP ~8/thread), descs prefetched 2 stages ahead,
//          no smem/syncthreads, __stcs streaming stores.

#define EB_VOCAB 50257
#define EB_DIM   1024
#define EB_BLANK 100
#define EB_S     4096
#define EB_B     4
#define EB_ROWS  (EB_B * EB_S)     // 16384
#define EB_GROUPS (EB_ROWS / 4)    // 4096
#define EB_GRID  592               // 4 blocks/SM * 148 SMs

__device__ int4 g_desc[EB_ROWS];

__device__ __forceinline__ int eb_tok(const void* __restrict__ x,
                                      int idx, bool is64) {
    if (is64) return (int)__ldg(((const long long*)x) + idx);
    return __ldg(((const int*)x) + idx);
}

// ---------------- prepass: build per-row descriptors ----------------
__global__ void __launch_bounds__(128)
blank_emb_prep(const void* __restrict__ x)
{
    const int row = blockIdx.x * 128 + threadIdx.x;
    if (row >= EB_ROWS) return;

    // dtype detection: int32 data read as int64 is >= 2^32 (or negative)
    // unless the paired token is 0; P(8 false positives) ~ (1/50257)^8 ~ 0.
    const long long* x64 = (const long long*)x;
    bool is64 = true;
#pragma unroll
    for (int i = 0; i < 8; i++) {
        long long v = __ldg(&x64[i]);
        if (v < 0 || v >= (long long)EB_VOCAB) is64 = false;
    }

    const int t    = row & (EB_S - 1);
    const int base = row & ~(EB_S - 1);

    int4 d;
    d.x = eb_tok(x, row, is64);
    d.y = -1; d.z = -1; d.w = -1;
    int* adds = &d.y;

#pragma unroll
    for (int j = 1; j <= 3; j++) {
        const int s = t - j;
        if (s >= 0) {
            // is_preblank[s] = (x[s+1]==BLANK) && (x[s]!=BLANK)
            if (eb_tok(x, base + s + 1, is64) == EB_BLANK) {
                const int xs = eb_tok(x, base + s, is64);
                if (xs != EB_BLANK) adds[j - 1] = xs;
            }
        }
    }
    g_desc[row] = d;
}

// ---------------- main: persistent pipelined gather-copy ----------------
__device__ __forceinline__ void eb_gather(const float* __restrict__ emb,
                                          int tok, int lane,
                                          float4& a, float4& b,
                                          float4& c, float4& d) {
    const float4* __restrict__ s =
        (const float4*)(emb + (size_t)tok * EB_DIM) + lane;
    a = __ldg(s);
    b = __ldg(s + 64);
    c = __ldg(s + 128);
    d = __ldg(s + 192);
}

__global__ void __launch_bounds__(256, 4)
blank_emb_main(const float* __restrict__ emb,
               float* __restrict__ out)
{
    const int tid    = threadIdx.x;
    const int sub    = tid >> 6;        // which of 4 rows in the group
    const int lane   = tid & 63;        // float4 slot within row
    const int stride = gridDim.x;

    int g0 = blockIdx.x;
    if (g0 >= EB_GROUPS) return;

    // ---- prologue: stage 0 desc+loads, descs prefetched 2 ahead ----
    int4 dc = __ldg(&g_desc[g0 * 4 + sub]);
    float4 v0, v1, v2, v3;
    eb_gather(emb, dc.x, lane, v0, v1, v2, v3);

    int g1 = g0 + stride;
    int4 dn = make_int4(0, -1, -1, -1);
    if (g1 < EB_GROUPS) dn = __ldg(&g_desc[g1 * 4 + sub]);

    int g2 = g1 + stride;
    int4 dn2 = make_int4(0, -1, -1, -1);
    if (g2 < EB_GROUPS) dn2 = __ldg(&g_desc[g2 * 4 + sub]);

    while (true) {
        // issue next group's gathers BEFORE consuming current (MLP ~8)
        float4 w0, w1, w2, w3;
        if (g1 < EB_GROUPS)
            eb_gather(emb, dn.x, lane, w0, w1, w2, w3);

        // rare preblank adds for current group (blank prob ~1/50257)
        if ((dc.y >= 0) | (dc.z >= 0) | (dc.w >= 0)) {
            const int a[3] = {dc.y, dc.z, dc.w};
#pragma unroll
            for (int j = 0; j < 3; j++) {
                if (a[j] >= 0) {
                    float4 e0, e1, e2, e3;
                    eb_gather(emb, a[j], lane, e0, e1, e2, e3);
                    v0.x += e0.x; v0.y += e0.y; v0.z += e0.z; v0.w += e0.w;
                    v1.x += e1.x; v1.y += e1.y; v1.z += e1.z; v1.w += e1.w;
                    v2.x += e2.x; v2.y += e2.y; v2.z += e2.z; v2.w += e2.w;
                    v3.x += e3.x; v3.y += e3.y; v3.z += e3.z; v3.w += e3.w;
                }
            }
        }

        // streaming store of current group
        {
            float4* __restrict__ dst =
                (float4*)(out + (size_t)(g0 * 4 + sub) * EB_DIM) + lane;
            __stcs(dst,       v0);
            __stcs(dst + 64,  v1);
            __stcs(dst + 128, v2);
            __stcs(dst + 192, v3);
        }

        if (g1 >= EB_GROUPS) break;

        // rotate pipeline
        g0 = g1; dc = dn;
        v0 = w0; v1 = w1; v2 = w2; v3 = w3;
        g1 = g2; dn = dn2;
        g2 = g1 + stride;
        if (g2 < EB_GROUPS) dn2 = __ldg(&g_desc[g2 * 4 + sub]);
    }
}

extern "C" void kernel_launch(void* const* d_in, const int* in_sizes, int n_in,
                              void* d_out, int out_size) {
    const void*  x   = d_in[0];               // [B,S] tokens (int64 or int32)
    const float* emb = (const float*)d_in[1]; // [VOCAB, DIM] fp32
    float*       out = (float*)d_out;         // [B,S,DIM] fp32

    blank_emb_prep<<<(EB_ROWS + 127) / 128, 128>>>(x);
    blank_emb_main<<<EB_GRID, 256>>>(emb, out);
}